// round 4
// baseline (speedup 1.0000x reference)
#include <cuda_runtime.h>

// RayPointRefiner: per-ray inverse-CDF fine sampling + merge with coarse samples.
// N_RAYS = 524288, N_PTS = 64, N_FINE = 64, output = [N_RAYS, 128] sorted.
//
// One warp per ray. Lane l owns elements 2l, 2l+1 of each 64-wide array.
//   1. float2-coalesced load of lengths (z) and ray_weights.
//   2. bins[i] = 0.5*(z[i]+z[i+1]), i=0..62  (63 mids)
//   3. w[j] = rw[j+1] + eps, j=0..61; warp-scan -> provably monotone cdf[0..62].
//   4. 64 inverse-CDF samples via 6-step binary search over 63 cdf entries.
//   5. Merge sorted z (64) with sorted samples (64) via rank placement using a
//      guarded pow2 COUNT search (all indices <= 63, count in [0,64]).
//   6. float4-coalesced store of 128 sorted values.

#define EPSF 1e-5f

constexpr int N_RAYS  = 524288;
constexpr int WPB     = 8;           // warps (rays) per block
constexpr int THREADS = WPB * 32;

struct alignas(16) RayShared {
    float cdf[64];   // cdf[0..62] used
    float bins[64];  // bins[0..62] used
    float zv[64];    // coarse z values (sorted)
    float zs[64];    // fine samples (sorted)
    float out[128];  // merged result
};

// count of elements in sorted a[0..63] with a[i] < v   (LT=true)
// or with a[i] <= v                                    (LT=false)
template <bool LT>
__device__ __forceinline__ int count64(const float* __restrict__ a, float v) {
    int c = 0;
    // step 64 first: indices accessed are c+step-1 <= 63 whenever c+step <= 64
    #pragma unroll
    for (int step = 64; step >= 1; step >>= 1) {
        const int nc = c + step;
        if (nc <= 64) {
            const float x = a[nc - 1];
            const bool cond = LT ? (x < v) : (x <= v);
            if (cond) c = nc;
        }
    }
    return c;
}

__global__ __launch_bounds__(THREADS) void refine_kernel(
    const float* __restrict__ lengths,
    const float* __restrict__ rw,
    float* __restrict__ out_g)
{
    __shared__ RayShared sh[WPB];
    const int lane = threadIdx.x & 31;
    const int warp = threadIdx.x >> 5;
    const int ray  = blockIdx.x * WPB + warp;
    RayShared& s = sh[warp];

    // ---- coalesced loads: lane l gets elements 2l, 2l+1 ----
    const float2 za = ((const float2*)lengths)[(size_t)ray * 32 + lane];
    const float2 wa = ((const float2*)rw)     [(size_t)ray * 32 + lane];

    ((float2*)s.zv)[lane] = za;

    const float znext = __shfl_down_sync(0xffffffffu, za.x, 1);
    const float wnext = __shfl_down_sync(0xffffffffu, wa.x, 1);

    // ---- bins (z midpoints), 63 values ----
    s.bins[2 * lane] = 0.5f * (za.x + za.y);
    if (lane < 31) s.bins[2 * lane + 1] = 0.5f * (za.y + znext);

    // ---- weights: w[2l] = rw[2l+1]+eps, w[2l+1] = rw[2l+2]+eps (lanes 0..30) ----
    float w0 = 0.0f, w1 = 0.0f;
    if (lane < 31) { w0 = wa.y + EPSF; w1 = wnext + EPSF; }
    const float pairsum = w0 + w1;

    // inclusive warp scan of pair sums
    float incl = pairsum;
    #pragma unroll
    for (int d = 1; d < 32; d <<= 1) {
        float v = __shfl_up_sync(0xffffffffu, incl, d);
        if (lane >= d) incl += v;
    }
    // exclusive prefix taken EXACTLY from neighbor's inclusive value, then one
    // sequential chain per lane -> cdf provably nondecreasing
    // (scan-vs-chain rounding << 1e-5 = min weight).
    float excl = __shfl_up_sync(0xffffffffu, incl, 1);
    if (lane == 0) excl = 0.0f;
    const float s1 = excl + w0;   // sum w[0..2l]
    const float s2 = s1 + w1;     // sum w[0..2l+1]

    const float total = __shfl_sync(0xffffffffu, s2, 30);
    const float invW  = 1.0f / total;

    if (lane == 0) s.cdf[0] = 0.0f;
    if (lane < 31) {
        s.cdf[2 * lane + 1] = s1 * invW;
        // exact 1.0 at the top so u=1.0 lands deterministically on bins[62]
        s.cdf[2 * lane + 2] = (lane == 30) ? 1.0f : s2 * invW;
    }
    __syncwarp();

    // ---- inverse-CDF sampling: u_k = k/63, searchsorted(cdf, u, 'right') ----
    // 63 entries: interval 63->31->15->7->3->1->0 closes in exactly 6 steps,
    // max index accessed = 62. Safe and complete.
    float zs0 = 0.0f, zs1 = 0.0f;
    #pragma unroll
    for (int q = 0; q < 2; q++) {
        const int k = 2 * lane + q;
        const float u = (k == 63) ? 1.0f : (float)k * (1.0f / 63.0f);
        int lo = 0, hi = 63;
        #pragma unroll
        for (int it = 0; it < 6; it++) {
            const int mid = (lo + hi) >> 1;
            const bool c = (s.cdf[mid] <= u);
            lo = c ? mid + 1 : lo;
            hi = c ? hi : mid;
        }
        // lo = inds in [1,63] (cdf[0]=0 <= u always)
        const int below = lo - 1;
        const int above = (lo < 62) ? lo : 62;
        const float cb = s.cdf[below];
        const float ca = s.cdf[above];
        const float bb = s.bins[below];
        const float ba = s.bins[above];
        float denom = ca - cb;
        if (denom < EPSF) denom = 1.0f;
        const float t = (u - cb) / denom;
        const float z = bb + t * (ba - bb);
        s.zs[k] = z;
        if (q == 0) zs0 = z; else zs1 = z;
    }
    __syncwarp();

    // ---- merge by rank placement (guarded count searches, bijective) ----
    // coarse z[i] -> out[i + #(zs < z[i])]
    s.out[2 * lane + 0 + count64<true>(s.zs, za.x)] = za.x;
    s.out[2 * lane + 1 + count64<true>(s.zs, za.y)] = za.y;
    // fine zs[j] -> out[j + #(zv <= zs[j])]
    s.out[2 * lane + 0 + count64<false>(s.zv, zs0)] = zs0;
    s.out[2 * lane + 1 + count64<false>(s.zv, zs1)] = zs1;
    __syncwarp();

    // ---- coalesced float4 store: 32 lanes x 16B = 512B = 128 floats ----
    const float4 o = ((const float4*)s.out)[lane];
    ((float4*)out_g)[(size_t)ray * 32 + lane] = o;
}

extern "C" void kernel_launch(void* const* d_in, const int* in_sizes, int n_in,
                              void* d_out, int out_size) {
    // metadata order: origins, directions, lengths, xys, ray_weights
    const float* lengths = (const float*)d_in[2];
    const float* weights = (const float*)d_in[4];
    float* out = (float*)d_out;
    refine_kernel<<<N_RAYS / WPB, THREADS>>>(lengths, weights, out);
}

// round 6
// speedup vs baseline: 1.2203x; 1.2203x over previous
#include <cuda_runtime.h>

// RayPointRefiner: per-ray inverse-CDF fine sampling + merge with coarse samples.
// N_RAYS = 524288, N_PTS = 64, N_FINE = 64, output = [N_RAYS, 128] sorted.
//
// One warp per ray; lane l owns elements 2l, 2l+1.
//   1. float2-coalesced loads of lengths (z) and ray_weights.
//   2. warp-scan -> provably monotone cdf[0..62]; shared holds cdf (search array)
//      and interleaved (cdf,bins) float2 pairs (gather array). 768B/ray total.
//   3. 64 inverse-CDF samples: 6-step binary search over 63 cdf entries + one
//      float2 gather pair for interpolation.
//   4. Final sort = register bitonic MERGE of [z ascending | zs descending]
//      (bitonic sequence): 5 shfl.xor stages + 2 in-lane stages. No shared.
//   5. Direct float4-coalesced store from registers.

#define EPSF 1e-5f

constexpr int N_RAYS  = 524288;
constexpr int WPB     = 8;           // warps (rays) per block
constexpr int THREADS = WPB * 32;
constexpr unsigned FULL = 0xffffffffu;

struct alignas(16) RayShared {
    float  cdf[64];   // cdf[0..62] used (search)
    float2 cb[64];    // (cdf[j], bins[j]) pairs, j=0..62 (gather)
};

__global__ __launch_bounds__(THREADS) void refine_kernel(
    const float* __restrict__ lengths,
    const float* __restrict__ rw,
    float* __restrict__ out_g)
{
    __shared__ RayShared sh[WPB];
    const int lane = threadIdx.x & 31;
    const int warp = threadIdx.x >> 5;
    const int ray  = blockIdx.x * WPB + warp;
    RayShared& s = sh[warp];

    // ---- coalesced loads: lane l gets elements 2l, 2l+1 ----
    const float2 za = ((const float2*)lengths)[(size_t)ray * 32 + lane];
    const float2 wa = ((const float2*)rw)     [(size_t)ray * 32 + lane];

    const float znext = __shfl_down_sync(FULL, za.x, 1);
    const float wnext = __shfl_down_sync(FULL, wa.x, 1);

    // bins (z midpoints): lane l owns bins[2l], bins[2l+1]
    const float bin0 = 0.5f * (za.x + za.y);
    const float bin1 = 0.5f * (za.y + znext);   // valid for lane<31

    // weights w[2l]=rw[2l+1]+eps, w[2l+1]=rw[2l+2]+eps (lanes 0..30)
    float w0 = 0.0f, w1 = 0.0f;
    if (lane < 31) { w0 = wa.y + EPSF; w1 = wnext + EPSF; }
    const float pairsum = w0 + w1;

    // inclusive warp scan of pair sums
    float incl = pairsum;
    #pragma unroll
    for (int d = 1; d < 32; d <<= 1) {
        float v = __shfl_up_sync(FULL, incl, d);
        if (lane >= d) incl += v;
    }
    // exclusive prefix exactly from neighbor; per-lane sequential chain keeps
    // cdf provably nondecreasing (ulp noise << eps = min weight).
    float excl = __shfl_up_sync(FULL, incl, 1);
    if (lane == 0) excl = 0.0f;
    const float s1 = excl + w0;                    // sum w[0..2l]
    const float total = __shfl_sync(FULL, incl, 31);
    const float invW  = 1.0f / total;

    const float c0 = excl * invW;                  // cdf[2l]
    const float c1 = s1   * invW;                  // cdf[2l+1]
    if (lane < 31) {
        ((float2*)s.cdf)[lane] = make_float2(c0, c1);
        ((float4*)s.cb )[lane] = make_float4(c0, bin0, c1, bin1);
    } else {
        s.cdf[62] = 1.0f;                          // exact top: u=1 -> bins[62]
        s.cb[62]  = make_float2(1.0f, bin0);       // bin0 here = bins[62]
    }
    __syncwarp();

    // ---- inverse-CDF sampling: u_k = k/63, searchsorted(cdf, u, 'right') ----
    // 63 entries: interval 63->31->15->7->3->1->0 closes in 6 steps, max idx 62.
    float zs0 = 0.0f, zs1 = 0.0f;
    #pragma unroll
    for (int q = 0; q < 2; q++) {
        const int k = 2 * lane + q;
        const float u = (k == 63) ? 1.0f : (float)k * (1.0f / 63.0f);
        int lo = 0, hi = 63;
        #pragma unroll
        for (int it = 0; it < 6; it++) {
            const int mid = (lo + hi) >> 1;
            const bool c = (s.cdf[mid] <= u);
            lo = c ? mid + 1 : lo;
            hi = c ? hi : mid;
        }
        const int below = lo - 1;                  // in [0,62]
        const int above = (lo < 62) ? lo : 62;
        const float2 pb = s.cb[below];             // (cdf_b, bins_b)
        const float2 pa = s.cb[above];             // (cdf_a, bins_a)
        float denom = pa.x - pb.x;
        if (denom < EPSF) denom = 1.0f;
        const float t = (u - pb.x) / denom;
        const float z = pb.y + t * (pa.y - pb.y);
        if (q == 0) zs0 = z; else zs1 = z;
    }

    // ---- redistribute into bitonic layout: element e = 4*lane + pos ----
    // lanes 0..15:  e in [0,64)   -> z ascending
    // lanes 16..31: e in [64,128) -> zs DESCENDING  => whole 128-seq is bitonic
    const int m    = lane - 16;
    const int srcA = (lane < 16) ? (2 * lane)     : (31 - 2 * m);
    const int srcB = (lane < 16) ? (2 * lane + 1) : (30 - 2 * m);
    const float azx = __shfl_sync(FULL, za.x, srcA);
    const float azy = __shfl_sync(FULL, za.y, srcA);
    const float bzx = __shfl_sync(FULL, za.x, srcB);
    const float bzy = __shfl_sync(FULL, za.y, srcB);
    const float as0 = __shfl_sync(FULL, zs0, srcA);
    const float as1 = __shfl_sync(FULL, zs1, srcA);
    const float bs0 = __shfl_sync(FULL, zs0, srcB);
    const float bs1 = __shfl_sync(FULL, zs1, srcB);

    float v0 = (lane < 16) ? azx : as1;   // zs[63-4m]
    float v1 = (lane < 16) ? azy : as0;   // zs[62-4m]
    float v2 = (lane < 16) ? bzx : bs1;   // zs[61-4m]
    float v3 = (lane < 16) ? bzy : bs0;   // zs[60-4m]

    // ---- bitonic merge: element strides 64,32,16,8,4 = lane masks 16..1 ----
    #pragma unroll
    for (int mask = 16; mask >= 1; mask >>= 1) {
        const bool keepmin = ((lane & mask) == 0);
        const float o0 = __shfl_xor_sync(FULL, v0, mask);
        const float o1 = __shfl_xor_sync(FULL, v1, mask);
        const float o2 = __shfl_xor_sync(FULL, v2, mask);
        const float o3 = __shfl_xor_sync(FULL, v3, mask);
        v0 = keepmin ? fminf(v0, o0) : fmaxf(v0, o0);
        v1 = keepmin ? fminf(v1, o1) : fmaxf(v1, o1);
        v2 = keepmin ? fminf(v2, o2) : fmaxf(v2, o2);
        v3 = keepmin ? fminf(v3, o3) : fmaxf(v3, o3);
    }
    // element stride 2 (in-lane): pairs (pos0,pos2), (pos1,pos3)
    {
        const float t0 = fminf(v0, v2), t2 = fmaxf(v0, v2);
        const float t1 = fminf(v1, v3), t3 = fmaxf(v1, v3);
        v0 = t0; v2 = t2; v1 = t1; v3 = t3;
    }
    // element stride 1 (in-lane): pairs (pos0,pos1), (pos2,pos3)
    {
        const float t0 = fminf(v0, v1), t1 = fmaxf(v0, v1);
        const float t2 = fminf(v2, v3), t3 = fmaxf(v2, v3);
        v0 = t0; v1 = t1; v2 = t2; v3 = t3;
    }

    // ---- direct coalesced float4 store from registers ----
    ((float4*)out_g)[(size_t)ray * 32 + lane] = make_float4(v0, v1, v2, v3);
}

extern "C" void kernel_launch(void* const* d_in, const int* in_sizes, int n_in,
                              void* d_out, int out_size) {
    // metadata order: origins, directions, lengths, xys, ray_weights
    const float* lengths = (const float*)d_in[2];
    const float* weights = (const float*)d_in[4];
    float* out = (float*)d_out;
    refine_kernel<<<N_RAYS / WPB, THREADS>>>(lengths, weights, out);
}

// round 8
// speedup vs baseline: 1.3471x; 1.1039x over previous
#include <cuda_runtime.h>

// RayPointRefiner: per-ray inverse-CDF fine sampling + merge with coarse samples.
// N_RAYS = 524288, N_PTS = 64, N_FINE = 64, output = [N_RAYS, 128] sorted.
//
// One warp per ray; lane l owns elements 2l, 2l+1.
// Key idea: u_k = k/63 is a UNIFORM grid, so searchsorted(cdf, u, 'right') is
// inverted analytically: threshold t_j = min{k : u_k >= cdf_j} = ceil(63*cdf_j)
// (exact after a +-1 fixup using the same rounded u values). CDF interval m
// owns samples k in [t_m, t_{m+1}) and interpolates them with register-resident
// constants, scattering results to a 64-float shared array. Final sort is a
// register bitonic MERGE of [z ascending | zs descending]. No binary searches,
// no cdf/bins shared arrays.

#define EPSF 1e-5f

constexpr int N_RAYS  = 524288;
constexpr int WPB     = 8;           // warps (rays) per block
constexpr int THREADS = WPB * 32;
constexpr unsigned FULL = 0xffffffffu;
constexpr float INV63 = 1.0f / 63.0f;

__device__ __forceinline__ float uval(int k) {
    return (k == 63) ? 1.0f : (float)k * INV63;
}

// exact t(c) = min{k in [0,63] : uval(k) >= c}, for c in (0, 1].
__device__ __forceinline__ int thresh(float c) {
    int t = (int)ceilf(c * 63.0f);
    t = max(1, min(t, 63));
    if (uval(t - 1) >= c)      t -= 1;   // candidate 1 too high
    else if (uval(t) < c)      t += 1;   // candidate 1 too low (t<=63 since c<=1)
    return t;
}

__global__ __launch_bounds__(THREADS) void refine_kernel(
    const float* __restrict__ lengths,
    const float* __restrict__ rw,
    float* __restrict__ out_g)
{
    __shared__ __align__(16) float zs_sh[WPB][64];
    const int lane = threadIdx.x & 31;
    const int warp = threadIdx.x >> 5;
    const int ray  = blockIdx.x * WPB + warp;
    float* zs = zs_sh[warp];

    // ---- coalesced loads: lane l gets elements 2l, 2l+1 ----
    const float2 za = ((const float2*)lengths)[(size_t)ray * 32 + lane];
    const float2 wa = ((const float2*)rw)     [(size_t)ray * 32 + lane];

    const float znext = __shfl_down_sync(FULL, za.x, 1);
    const float wnext = __shfl_down_sync(FULL, wa.x, 1);

    // bins (z midpoints): lane l owns bins[2l], bins[2l+1]; binN = bins[2l+2]
    const float bin0 = 0.5f * (za.x + za.y);
    float       bin1 = 0.5f * (za.y + znext);          // lanes<31 valid
    const float binN = __shfl_down_sync(FULL, bin0, 1); // lanes<31 valid

    // weights w[2l]=rw[2l+1]+eps, w[2l+1]=rw[2l+2]+eps (lanes 0..30)
    float w0 = 0.0f, w1 = 0.0f;
    if (lane < 31) { w0 = wa.y + EPSF; w1 = wnext + EPSF; }
    const float pairsum = w0 + w1;

    // inclusive warp scan of pair sums
    float incl = pairsum;
    #pragma unroll
    for (int d = 1; d < 32; d <<= 1) {
        float v = __shfl_up_sync(FULL, incl, d);
        if (lane >= d) incl += v;
    }
    float excl = __shfl_up_sync(FULL, incl, 1);
    if (lane == 0) excl = 0.0f;
    const float sA = excl + w0;     // sum w[0..2l]   (sequential chain keeps
    const float sB = sA + w1;       // sum w[0..2l+1]  cdf provably monotone)
    const float total = __shfl_sync(FULL, incl, 31);
    const float invW  = 1.0f / total;

    // cdf values owned by this lane: cdf[2l]=c0, cdf[2l+1]=c1, cdf[2l+2]=c2
    float c0 = excl * invW;
    float c1 = sA   * invW;
    const float c2 = (lane == 30) ? 1.0f : sB * invW;  // exact 1.0 at cdf[62]
    if (lane == 31) { c0 = 1.0f; c1 = 1.0f; bin1 = bin0; }  // interval 62 degenerates to bins[62]

    // thresholds t_{2l+1}, t_{2l+2} (lanes 0..30)
    int t1 = 64, t2 = 64;
    if (lane < 31) { t1 = thresh(c1); t2 = thresh(c2); }
    int tA_lo = __shfl_up_sync(FULL, t2, 1);   // t_{2l}
    if (lane == 0) tA_lo = 0;
    const int tA_hi = (lane == 31) ? 64 : t1;  // t_{2l+1} (t_63 := 64 sentinel)

    // interval 2l: (cdf_b,cdf_a,bins_b,bins_a) = (c0,c1,bin0,bin1)
    {
        float d = c1 - c0; if (d < EPSF) d = 1.0f;
        const float r = 1.0f / d;
        const float dbin = bin1 - bin0;
        for (int k = tA_lo; k < tA_hi; ++k) {
            const float t = (uval(k) - c0) * r;
            zs[k] = fmaf(t, dbin, bin0);
        }
    }
    // interval 2l+1: (c1,c2,bin1,binN), lanes 0..30
    if (lane < 31) {
        float d = c2 - c1; if (d < EPSF) d = 1.0f;
        const float r = 1.0f / d;
        const float dbin = binN - bin1;
        for (int k = t1; k < t2; ++k) {
            const float t = (uval(k) - c1) * r;
            zs[k] = fmaf(t, dbin, bin1);
        }
    }
    __syncwarp();

    // ---- bitonic layout: element e = 4*lane + pos ----
    // lanes 0..15:  z[4l..4l+3] ascending (via shuffles from pair owners)
    // lanes 16..31: zs[63-4m..60-4m] DESCENDING (reversed LDS.128)
    const int srcA = 2 * (lane & 15);
    const float azx = __shfl_sync(FULL, za.x, srcA);
    const float azy = __shfl_sync(FULL, za.y, srcA);
    const float bzx = __shfl_sync(FULL, za.x, srcA + 1);
    const float bzy = __shfl_sync(FULL, za.y, srcA + 1);

    float v0, v1, v2, v3;
    if (lane < 16) {
        v0 = azx; v1 = azy; v2 = bzx; v3 = bzy;
    } else {
        const int m = lane - 16;
        const float4 q = *(const float4*)&zs[60 - 4 * m];
        v0 = q.w; v1 = q.z; v2 = q.y; v3 = q.x;
    }

    // ---- bitonic merge: element strides 64..4 = lane masks 16..1 ----
    #pragma unroll
    for (int mask = 16; mask >= 1; mask >>= 1) {
        const bool keepmin = ((lane & mask) == 0);
        const float o0 = __shfl_xor_sync(FULL, v0, mask);
        const float o1 = __shfl_xor_sync(FULL, v1, mask);
        const float o2 = __shfl_xor_sync(FULL, v2, mask);
        const float o3 = __shfl_xor_sync(FULL, v3, mask);
        v0 = keepmin ? fminf(v0, o0) : fmaxf(v0, o0);
        v1 = keepmin ? fminf(v1, o1) : fmaxf(v1, o1);
        v2 = keepmin ? fminf(v2, o2) : fmaxf(v2, o2);
        v3 = keepmin ? fminf(v3, o3) : fmaxf(v3, o3);
    }
    { // element stride 2 (in-lane)
        const float t0 = fminf(v0, v2), t2 = fmaxf(v0, v2);
        const float t1 = fminf(v1, v3), t3 = fmaxf(v1, v3);
        v0 = t0; v2 = t2; v1 = t1; v3 = t3;
    }
    { // element stride 1 (in-lane)
        const float t0 = fminf(v0, v1), t1 = fmaxf(v0, v1);
        const float t2 = fminf(v2, v3), t3 = fmaxf(v2, v3);
        v0 = t0; v1 = t1; v2 = t2; v3 = t3;
    }

    // ---- direct coalesced float4 store from registers ----
    ((float4*)out_g)[(size_t)ray * 32 + lane] = make_float4(v0, v1, v2, v3);
}

extern "C" void kernel_launch(void* const* d_in, const int* in_sizes, int n_in,
                              void* d_out, int out_size) {
    // metadata order: origins, directions, lengths, xys, ray_weights
    const float* lengths = (const float*)d_in[2];
    const float* weights = (const float*)d_in[4];
    float* out = (float*)d_out;
    refine_kernel<<<N_RAYS / WPB, THREADS>>>(lengths, weights, out);
}